// round 14
// baseline (speedup 1.0000x reference)
#include <cuda_runtime.h>
#include <cuda_bf16.h>
#include <math.h>
#include <stdint.h>

#define NN 4096
#define DD 256
#define HH 4
#define HD 64
#define D3 768
#define BUCKET 96

#define CVT_BF16X2_F32(result, a, b) \
    asm("cvt.rn.satfinite.bf16x2.f32 %0, %1, %2;" : "=r"(result) : "f"(b), "f"(a))

__device__ __forceinline__ float fexp2(float x) {
    float y;
    asm("ex2.approx.ftz.f32 %0, %1;" : "=f"(y) : "f"(x));
    return y;
}
__device__ __forceinline__ uint32_t smem_u32(const void* p) {
    uint32_t a;
    asm("{ .reg .u64 t; cvta.to.shared.u64 t, %1; cvt.u32.u64 %0, t; }" : "=r"(a) : "l"(p));
    return a;
}
#define CP_ASYNC16(dst, src) \
    asm volatile("cp.async.cg.shared.global [%0], [%1], 16;" :: "r"(dst), "l"(src))
#define CP_COMMIT() asm volatile("cp.async.commit_group;" ::: "memory")
#define CP_WAIT(n)  asm volatile("cp.async.wait_group %0;" :: "n"(n) : "memory")

__device__ __forceinline__ void mma16816(float c[4],
                                         uint32_t a0, uint32_t a1, uint32_t a2, uint32_t a3,
                                         uint32_t b0, uint32_t b1) {
    asm volatile("mma.sync.aligned.m16n8k16.row.col.f32.bf16.bf16.f32 "
                 "{%0,%1,%2,%3}, {%4,%5,%6,%7}, {%8,%9}, {%0,%1,%2,%3};"
                 : "+f"(c[0]), "+f"(c[1]), "+f"(c[2]), "+f"(c[3])
                 : "r"(a0), "r"(a1), "r"(a2), "r"(a3), "r"(b0), "r"(b1));
}
__device__ __forceinline__ void mma1688t(float c[4],
                                         uint32_t a0, uint32_t a1, uint32_t a2, uint32_t a3,
                                         uint32_t b0, uint32_t b1) {
    asm volatile("mma.sync.aligned.m16n8k8.row.col.f32.tf32.tf32.f32 "
                 "{%0,%1,%2,%3}, {%4,%5,%6,%7}, {%8,%9}, {%0,%1,%2,%3};"
                 : "+f"(c[0]), "+f"(c[1]), "+f"(c[2]), "+f"(c[3])
                 : "r"(a0), "r"(a1), "r"(a2), "r"(a3), "r"(b0), "r"(b1));
}

// ======================= scratch (device globals; BSS-zeroed at load) =======
__device__ float g_h   [NN * DD];
__device__ float g_x1  [NN * DD];
__device__ float g_attn[NN * DD];
__device__ float g_ao  [NN * DD];
__device__ float g_x2  [NN * DD];
__device__ float g_h1  [NN * 2 * DD];
__device__ float g_f2  [NN * DD];
__device__ float g_dinv[NN];
__device__ int   g_deg [NN];
__device__ int   g_degc[NN];
__device__ int   g_ebuf[NN * BUCKET];
__device__ __align__(16) __nv_bfloat16 g_qb [HH * NN * HD];
__device__ __align__(16) __nv_bfloat16 g_kb [HH * NN * HD];
__device__ __align__(16) __nv_bfloat16 g_vtb[HH * HD * NN];

#define QSCALE (0.125f * 1.4426950408889634f)

// ======================= bucketed CSR (one atomic pass) =====================
__global__ void count_fill_kernel(const int* __restrict__ src, const int* __restrict__ dst,
                                  int* __restrict__ deg, int* __restrict__ ebuf, int E) {
    int e = blockIdx.x * blockDim.x + threadIdx.x;
    if (e < E) {
        int d = dst[e];
        int pos = atomicAdd(&deg[d], 1);
        ebuf[d * BUCKET + pos] = src[e];
    }
}
__global__ void dinv_kernel(int* __restrict__ deg, int* __restrict__ degc,
                            float* __restrict__ dinv) {
    int i = blockIdx.x * blockDim.x + threadIdx.x;
    if (i < NN) {
        int d = deg[i];
        dinv[i] = rsqrtf((float)d + 1.0f);
        degc[i] = d;
        deg[i] = 0;
    }
}

// ======================= fused GCN gather + self-loop + LN1 =================
// 64 threads, each owns 4 columns (float4). Per edge per thread:
// 1 LDS.64 bcast + 1 shift + 1 LDG.128 + 4 FFMA -> 4 elements.
__global__ __launch_bounds__(64)
void gcn_ln_kernel(const float* __restrict__ x, const float* __restrict__ h,
                   const float* __restrict__ dinv,
                   const int* __restrict__ degc, const int* __restrict__ ebuf,
                   const float* __restrict__ b_gcn,
                   const float* __restrict__ gln, const float* __restrict__ beta,
                   float* __restrict__ x1) {
    const int i = blockIdx.x;
    const int tid = threadIdx.x;

    __shared__ __align__(8) float2 s_ec[BUCKET];   // (.x = src bits, .y = coef)
    __shared__ float ws1[2], ws2[2], bc[2];
    __shared__ int   s_dg;
    __shared__ float s_di;

    if (tid == 0) { s_dg = degc[i]; s_di = dinv[i]; }
    __syncthreads();
    const int dg = s_dg;
    const float di = s_di;

    for (int j = tid; j < dg; j += 64) {
        int s = ebuf[i * BUCKET + j];
        float2 ec;
        ec.x = __int_as_float(s);
        ec.y = dinv[s] * di;
        s_ec[j] = ec;
    }
    __syncthreads();

    const char* hb = (const char*)(h + 4 * tid);
    float4 acc = make_float4(0.f, 0.f, 0.f, 0.f);
    int j = 0;
    for (; j + 3 < dg; j += 4) {
        float2 e0 = s_ec[j],     e1 = s_ec[j + 1];
        float2 e2 = s_ec[j + 2], e3 = s_ec[j + 3];
        float4 v0 = *(const float4*)(hb + ((uint32_t)__float_as_int(e0.x) << 10));
        float4 v1 = *(const float4*)(hb + ((uint32_t)__float_as_int(e1.x) << 10));
        float4 v2 = *(const float4*)(hb + ((uint32_t)__float_as_int(e2.x) << 10));
        float4 v3 = *(const float4*)(hb + ((uint32_t)__float_as_int(e3.x) << 10));
        acc.x += v0.x * e0.y + v1.x * e1.y + v2.x * e2.y + v3.x * e3.y;
        acc.y += v0.y * e0.y + v1.y * e1.y + v2.y * e2.y + v3.y * e3.y;
        acc.z += v0.z * e0.y + v1.z * e1.y + v2.z * e2.y + v3.z * e3.y;
        acc.w += v0.w * e0.y + v1.w * e1.y + v2.w * e2.y + v3.w * e3.y;
    }
    for (; j < dg; j++) {
        float2 e = s_ec[j];
        float4 v = *(const float4*)(hb + ((uint32_t)__float_as_int(e.x) << 10));
        acc.x += v.x * e.y; acc.y += v.y * e.y;
        acc.z += v.z * e.y; acc.w += v.w * e.y;
    }

    const float dii = di * di;
    float4 xv = *(const float4*)&x[(size_t)i * DD + 4 * tid];
    float4 hv = *(const float4*)&h[(size_t)i * DD + 4 * tid];
    float4 bg = *(const float4*)&b_gcn[4 * tid];
    float4 v;
    v.x = xv.x + acc.x + hv.x * dii + bg.x;
    v.y = xv.y + acc.y + hv.y * dii + bg.y;
    v.z = xv.z + acc.z + hv.z * dii + bg.z;
    v.w = xv.w + acc.w + hv.w * dii + bg.w;

    // LN over 256 values held 4-per-thread across 64 threads (2 warps)
    float s1v = v.x + v.y + v.z + v.w;
    float s2v = v.x * v.x + v.y * v.y + v.z * v.z + v.w * v.w;
    #pragma unroll
    for (int off = 16; off > 0; off >>= 1) {
        s1v += __shfl_xor_sync(0xffffffffu, s1v, off);
        s2v += __shfl_xor_sync(0xffffffffu, s2v, off);
    }
    int w = tid >> 5;
    if ((tid & 31) == 0) { ws1[w] = s1v; ws2[w] = s2v; }
    __syncthreads();
    if (tid == 0) {
        float t1 = ws1[0] + ws1[1];
        float t2 = ws2[0] + ws2[1];
        float mean = t1 * (1.0f / DD);
        float var  = t2 * (1.0f / DD) - mean * mean;
        bc[0] = mean; bc[1] = rsqrtf(var + 1e-5f);
    }
    __syncthreads();
    float4 gv = *(const float4*)&gln[4 * tid];
    float4 bv = *(const float4*)&beta[4 * tid];
    float4 o;
    o.x = (v.x - bc[0]) * bc[1] * gv.x + bv.x;
    o.y = (v.y - bc[0]) * bc[1] * gv.y + bv.y;
    o.z = (v.z - bc[0]) * bc[1] * gv.z + bv.z;
    o.w = (v.w - bc[0]) * bc[1] * gv.w + bv.w;
    *(float4*)&x1[(size_t)i * DD + 4 * tid] = o;
}

// ======================= layernorm (residual) ================================
__global__ void ln_kernel(const float* __restrict__ a, const float* __restrict__ b,
                          const float* __restrict__ g, const float* __restrict__ beta,
                          float* __restrict__ out) {
    int r = blockIdx.x, d = threadIdx.x;
    float v = a[r * DD + d] + b[r * DD + d];
    float s1 = v, s2 = v * v;
    #pragma unroll
    for (int off = 16; off > 0; off >>= 1) {
        s1 += __shfl_xor_sync(0xffffffffu, s1, off);
        s2 += __shfl_xor_sync(0xffffffffu, s2, off);
    }
    __shared__ float ws1[8], ws2[8], bc[2];
    int w = threadIdx.x >> 5;
    if ((threadIdx.x & 31) == 0) { ws1[w] = s1; ws2[w] = s2; }
    __syncthreads();
    if (threadIdx.x == 0) {
        float t1 = 0.f, t2 = 0.f;
        #pragma unroll
        for (int i = 0; i < 8; i++) { t1 += ws1[i]; t2 += ws2[i]; }
        float mean = t1 * (1.0f / DD);
        float var  = t2 * (1.0f / DD) - mean * mean;
        bc[0] = mean; bc[1] = rsqrtf(var + 1e-5f);
    }
    __syncthreads();
    out[r * DD + d] = (v - bc[0]) * bc[1] * g[d] + beta[d];
}

// ======================= tf32 HMMA GEMM, 3-stage cp.async ===================
#define ALD 36
#define BLD 72
#define ASZ (64 * ALD)
#define BSZ (32 * BLD)
#define GSTAGES 3
#define GEMM_SMEM ((GSTAGES * (ASZ + BSZ)) * 4)
template <int MODE>
__global__ __launch_bounds__(256)
void tgemm_kernel(const float* __restrict__ A, const float* __restrict__ B,
                  const float* __restrict__ bias, float* __restrict__ C,
                  int M, int N, int K) {
    extern __shared__ float dsm[];
    float* As = dsm;
    float* Bs = dsm + GSTAGES * ASZ;
    const int tid = threadIdx.x;
    const int lane = tid & 31;
    const int g = lane >> 2, t = lane & 3;
    const int wid = tid >> 5;
    const int wm = (wid >> 2) * 32;
    const int wn = (wid & 3) * 16;
    const int bm = blockIdx.y * 64, bn = blockIdx.x * 64;

    const uint32_t sA = smem_u32(As);
    const uint32_t sB = smem_u32(Bs);
    const int nk = K / 32;

    auto load_stage = [&](int k0, int s) {
        #pragma unroll
        for (int i = 0; i < 2; i++) {
            int p = tid + 256 * i;
            int row = p >> 3, c = p & 7;
            uint32_t dst = sA + (uint32_t)(s * ASZ + row * ALD + c * 4) * 4u;
            CP_ASYNC16(dst, &A[(size_t)(bm + row) * K + k0 + c * 4]);
        }
        #pragma unroll
        for (int i = 0; i < 2; i++) {
            int p = tid + 256 * i;
            int row = p >> 4, c = p & 15;
            uint32_t dst = sB + (uint32_t)(s * BSZ + row * BLD + c * 4) * 4u;
            CP_ASYNC16(dst, &B[(size_t)(k0 + row) * N + bn + c * 4]);
        }
        CP_COMMIT();
    };

    float acc[2][2][4] = {};

    load_stage(0, 0);
    if (nk > 1) load_stage(32, 1); else CP_COMMIT();
    for (int it = 0; it < nk; it++) {
        if (it + 2 < nk) load_stage((it + 2) * 32, (it + 2) % GSTAGES);
        else             CP_COMMIT();
        CP_WAIT(2);
        __syncthreads();

        const float* a_ = As + (it % GSTAGES) * ASZ;
        const float* b_ = Bs + (it % GSTAGES) * BSZ;
        #pragma unroll
        for (int kk = 0; kk < 4; kk++) {
            const int kb = kk * 8;
            uint32_t a[2][4];
            #pragma unroll
            for (int mi = 0; mi < 2; mi++) {
                int r = wm + mi * 16 + g;
                a[mi][0] = __float_as_uint(a_[r * ALD + kb + t]);
                a[mi][1] = __float_as_uint(a_[(r + 8) * ALD + kb + t]);
                a[mi][2] = __float_as_uint(a_[r * ALD + kb + t + 4]);
                a[mi][3] = __float_as_uint(a_[(r + 8) * ALD + kb + t + 4]);
            }
            #pragma unroll
            for (int nj = 0; nj < 2; nj++) {
                int cn = wn + nj * 8 + g;
                uint32_t b0 = __float_as_uint(b_[(kb + t) * BLD + cn]);
                uint32_t b1 = __float_as_uint(b_[(kb + t + 4) * BLD + cn]);
                mma1688t(acc[0][nj], a[0][0], a[0][1], a[0][2], a[0][3], b0, b1);
                mma1688t(acc[1][nj], a[1][0], a[1][1], a[1][2], a[1][3], b0, b1);
            }
        }
        __syncthreads();
    }

    #pragma unroll
    for (int nj = 0; nj < 2; nj++) {
        int col = bn + wn + nj * 8 + 2 * t;
        float2 bb = make_float2(0.f, 0.f);
        if (bias) bb = *(const float2*)&bias[col];
        #pragma unroll
        for (int mi = 0; mi < 2; mi++) {
            int row = bm + wm + mi * 16 + g;
            float2 v0 = make_float2(acc[mi][nj][0] + bb.x, acc[mi][nj][1] + bb.y);
            float2 v1 = make_float2(acc[mi][nj][2] + bb.x, acc[mi][nj][3] + bb.y);
            if (MODE == 1) {
                v0.x = fmaxf(v0.x, 0.f); v0.y = fmaxf(v0.y, 0.f);
                v1.x = fmaxf(v1.x, 0.f); v1.y = fmaxf(v1.y, 0.f);
            }
            if (MODE == 2) {
                if (col < 256) {            // Q, scaled
                    int hh = col >> 6, d = col & 63;
                    uint32_t p0, p1;
                    CVT_BF16X2_F32(p0, v0.x * QSCALE, v0.y * QSCALE);
                    CVT_BF16X2_F32(p1, v1.x * QSCALE, v1.y * QSCALE);
                    *(uint32_t*)&g_qb[(size_t)(hh * NN + row) * HD + d] = p0;
                    *(uint32_t*)&g_qb[(size_t)(hh * NN + row + 8) * HD + d] = p1;
                } else if (col < 512) {     // K
                    int c = col - 256;
                    int hh = c >> 6, d = c & 63;
                    uint32_t p0, p1;
                    CVT_BF16X2_F32(p0, v0.x, v0.y);
                    CVT_BF16X2_F32(p1, v1.x, v1.y);
                    *(uint32_t*)&g_kb[(size_t)(hh * NN + row) * HD + d] = p0;
                    *(uint32_t*)&g_kb[(size_t)(hh * NN + row + 8) * HD + d] = p1;
                } else {                    // V, transposed
                    int c = col - 512;
                    int hh = c >> 6, d = c & 63;
                    __nv_bfloat16* v_d0 = g_vtb + (size_t)(hh * HD + d) * NN;
                    __nv_bfloat16* v_d1 = g_vtb + (size_t)(hh * HD + d + 1) * NN;
                    v_d0[row]     = __float2bfloat16(v0.x);
                    v_d1[row]     = __float2bfloat16(v0.y);
                    v_d0[row + 8] = __float2bfloat16(v1.x);
                    v_d1[row + 8] = __float2bfloat16(v1.y);
                }
            } else {
                *(float2*)&C[(size_t)row * N + col] = v0;
                *(float2*)&C[(size_t)(row + 8) * N + col] = v1;
            }
        }
    }
}

// ======================= HMMA flash attention ================================
#define QROWB 144
#define QS_BYTES (64 * QROWB)
#define KV_BYTES (64 * QROWB)
#define ATT_SMEM (QS_BYTES + 4 * KV_BYTES)
__global__ __launch_bounds__(128)
void attn_mma_kernel(float* __restrict__ attn_out) {
    extern __shared__ __align__(16) uint8_t asmem[];
    uint8_t* Qs = asmem;
    uint8_t* Ks = asmem + QS_BYTES;
    uint8_t* Vs = asmem + QS_BYTES + 2 * KV_BYTES;

    const int tid = threadIdx.x;
    const int wid = tid >> 5;
    const int lane = tid & 31;
    const int g = lane >> 2;
    const int t = lane & 3;
    const int hh = blockIdx.y;
    const int qt = blockIdx.x;

    const uint32_t sK = smem_u32(Ks);
    const uint32_t sV = smem_u32(Vs);

    auto load_kv = [&](int kt, int s) {
        const char* kbase = (const char*)(g_kb + (size_t)(hh * NN + kt * 64) * HD);
        #pragma unroll
        for (int i = 0; i < 4; i++) {
            int p = tid + 128 * i;
            int row = p >> 3, c = p & 7;
            CP_ASYNC16(sK + (uint32_t)(s * KV_BYTES + row * QROWB + c * 16),
                       kbase + row * 128 + c * 16);
            const char* vbase = (const char*)(g_vtb + (size_t)(hh * HD + row) * NN + kt * 64);
            CP_ASYNC16(sV + (uint32_t)(s * KV_BYTES + row * QROWB + c * 16),
                       vbase + c * 16);
        }
        CP_COMMIT();
    };

    {
        const uint4* src = (const uint4*)(g_qb + (size_t)(hh * NN + qt * 64) * HD);
        #pragma unroll
        for (int i = 0; i < 4; i++) {
            int p = tid + 128 * i;
            int row = p >> 3, c = p & 7;
            *(uint4*)&Qs[row * QROWB + c * 16] = src[p];
        }
    }
    load_kv(0, 0);
    __syncthreads();

    uint32_t qf[4][4];
    {
        int r0 = wid * 16 + g;
        #pragma unroll
        for (int kc = 0; kc < 4; kc++) {
            int cb = (kc * 16 + 2 * t) * 2;
            qf[kc][0] = *(const uint32_t*)&Qs[r0 * QROWB + cb];
            qf[kc][1] = *(const uint32_t*)&Qs[(r0 + 8) * QROWB + cb];
            qf[kc][2] = *(const uint32_t*)&Qs[r0 * QROWB + cb + 16];
            qf[kc][3] = *(const uint32_t*)&Qs[(r0 + 8) * QROWB + cb + 16];
        }
    }

    float O[8][4];
    #pragma unroll
    for (int n = 0; n < 8; n++)
        #pragma unroll
        for (int i = 0; i < 4; i++) O[n][i] = 0.f;
    float l0 = 0.f, l1 = 0.f;

    for (int kt = 0; kt < NN / 64; kt++) {
        if (kt + 1 < NN / 64) load_kv(kt + 1, (kt + 1) & 1);
        else                  CP_COMMIT();
        CP_WAIT(1);
        __syncthreads();

        const uint8_t* kb = Ks + (kt & 1) * KV_BYTES;
        const uint8_t* vb = Vs + (kt & 1) * KV_BYTES;

        float S[8][4];
        #pragma unroll
        for (int n = 0; n < 8; n++)
            #pragma unroll
            for (int i = 0; i < 4; i++) S[n][i] = 0.f;
        #pragma unroll
        for (int kc = 0; kc < 4; kc++) {
            int cb = (kc * 16 + 2 * t) * 2;
            #pragma unroll
            for (int n = 0; n < 8; n++) {
                uint32_t b0 = *(const uint32_t*)&kb[(n * 8 + g) * QROWB + cb];
                uint32_t b1 = *(const uint32_t*)&kb[(n * 8 + g) * QROWB + cb + 16];
                mma16816(S[n], qf[kc][0], qf[kc][1], qf[kc][2], qf[kc][3], b0, b1);
            }
        }

        uint32_t pb[8][2];
        #pragma unroll
        for (int n = 0; n < 8; n++) {
            float p0 = fexp2(S[n][0]);
            float p1 = fexp2(S[n][1]);
            float p2 = fexp2(S[n][2]);
            float p3 = fexp2(S[n][3]);
            l0 += p0 + p1; l1 += p2 + p3;
            CVT_BF16X2_F32(pb[n][0], p0, p1);
            CVT_BF16X2_F32(pb[n][1], p2, p3);
        }

        #pragma unroll
        for (int kc = 0; kc < 4; kc++) {
            uint32_t a0 = pb[2 * kc][0], a1 = pb[2 * kc][1];
            uint32_t a2 = pb[2 * kc + 1][0], a3 = pb[2 * kc + 1][1];
            int cb = (kc * 16 + 2 * t) * 2;
            #pragma unroll
            for (int n = 0; n < 8; n++) {
                uint32_t b0 = *(const uint32_t*)&vb[(n * 8 + g) * QROWB + cb];
                uint32_t b1 = *(const uint32_t*)&vb[(n * 8 + g) * QROWB + cb + 16];
                mma16816(O[n], a0, a1, a2, a3, b0, b1);
            }
        }
        __syncthreads();
    }

    l0 += __shfl_xor_sync(0xffffffffu, l0, 1);
    l0 += __shfl_xor_sync(0xffffffffu, l0, 2);
    l1 += __shfl_xor_sync(0xffffffffu, l1, 1);
    l1 += __shfl_xor_sync(0xffffffffu, l1, 2);

    float inv0 = 1.0f / l0, inv1 = 1.0f / l1;
    int r0 = qt * 64 + wid * 16 + g;
    #pragma unroll
    for (int n = 0; n < 8; n++) {
        int dcol = hh * HD + n * 8 + 2 * t;
        float2 v0 = make_float2(O[n][0] * inv0, O[n][1] * inv0);
        float2 v1 = make_float2(O[n][2] * inv1, O[n][3] * inv1);
        *(float2*)&attn_out[(size_t)r0 * DD + dcol] = v0;
        *(float2*)&attn_out[(size_t)(r0 + 8) * DD + dcol] = v1;
    }
}

// ======================= launch =============================================
static float* sym_f(const void* sym) {
    void* p = nullptr;
    cudaGetSymbolAddress(&p, sym);
    return (float*)p;
}

extern "C" void kernel_launch(void* const* d_in, const int* in_sizes, int n_in,
                              void* d_out, int out_size) {
    const float* x      = (const float*)d_in[0];
    const int*   edges  = (const int*)  d_in[1];
    const float* W_gcn  = (const float*)d_in[2];
    const float* b_gcn  = (const float*)d_in[3];
    const float* w_qkv  = (const float*)d_in[4];
    const float* b_qkv  = (const float*)d_in[5];
    const float* w_out  = (const float*)d_in[6];
    const float* b_out  = (const float*)d_in[7];
    const float* g1l    = (const float*)d_in[8];
    const float* beta1l = (const float*)d_in[9];
    const float* g1a    = (const float*)d_in[10];
    const float* beta1a = (const float*)d_in[11];
    const float* W1     = (const float*)d_in[12];
    const float* bf1    = (const float*)d_in[13];
    const float* W2     = (const float*)d_in[14];
    const float* bf2    = (const float*)d_in[15];
    const float* g2     = (const float*)d_in[16];
    const float* beta2  = (const float*)d_in[17];
    float* out = (float*)d_out;

    float* p_h    = sym_f(g_h);
    float* p_x1   = sym_f(g_x1);
    float* p_attn = sym_f(g_attn);
    float* p_ao   = sym_f(g_ao);
    float* p_x2   = sym_f(g_x2);
    float* p_h1   = sym_f(g_h1);
    float* p_f2   = sym_f(g_f2);
    float* p_dinv = sym_f(g_dinv);
    int*   p_deg  = (int*)sym_f(g_deg);
    int*   p_degc = (int*)sym_f(g_degc);
    int*   p_ebuf = (int*)sym_f(g_ebuf);

    const int E = in_sizes[1] / 2;
    const int* e_src = edges;
    const int* e_dst = edges + E;

    cudaFuncSetAttribute(tgemm_kernel<0>, cudaFuncAttributeMaxDynamicSharedMemorySize, GEMM_SMEM);
    cudaFuncSetAttribute(tgemm_kernel<1>, cudaFuncAttributeMaxDynamicSharedMemorySize, GEMM_SMEM);
    cudaFuncSetAttribute(tgemm_kernel<2>, cudaFuncAttributeMaxDynamicSharedMemorySize, GEMM_SMEM);
    cudaFuncSetAttribute(attn_mma_kernel, cudaFuncAttributeMaxDynamicSharedMemorySize, ATT_SMEM);

    // ---- fork: CSR build (stream s2) runs concurrently with GCN GEMM ----
    cudaStream_t s2;
    cudaStreamCreate(&s2);
    cudaEvent_t eFork, eJoin;
    cudaEventCreateWithFlags(&eFork, cudaEventDisableTiming);
    cudaEventCreateWithFlags(&eJoin, cudaEventDisableTiming);

    cudaEventRecord(eFork, 0);
    cudaStreamWaitEvent(s2, eFork, 0);
    count_fill_kernel<<<(E + 255) / 256, 256, 0, s2>>>(e_src, e_dst, p_deg, p_ebuf, E);
    dinv_kernel<<<NN / 256, 256, 0, s2>>>(p_deg, p_degc, p_dinv);
    cudaEventRecord(eJoin, s2);

    // main stream: h = x @ W_gcn (independent of CSR)
    tgemm_kernel<0><<<dim3(DD / 64, NN / 64), 256, GEMM_SMEM>>>(x, W_gcn, nullptr, p_h, NN, DD, DD);

    cudaStreamWaitEvent(0, eJoin, 0);   // join before gcn_ln

    gcn_ln_kernel<<<NN, 64>>>(x, p_h, p_dinv, p_degc, p_ebuf, b_gcn, g1l, beta1l, p_x1);

    tgemm_kernel<2><<<dim3(D3 / 64, NN / 64), 256, GEMM_SMEM>>>(p_x1, w_qkv, b_qkv, nullptr, NN, D3, DD);

    attn_mma_kernel<<<dim3(NN / 64, HH), 128, ATT_SMEM>>>(p_attn);

    tgemm_kernel<0><<<dim3(DD / 64, NN / 64), 256, GEMM_SMEM>>>(p_attn, w_out, b_out, p_ao, NN, DD, DD);

    ln_kernel<<<NN, 256>>>(p_x1, p_ao, g1a, beta1a, p_x2);

    tgemm_kernel<1><<<dim3(2 * DD / 64, NN / 64), 256, GEMM_SMEM>>>(p_x2, W1, bf1, p_h1, NN, 2 * DD, DD);
    tgemm_kernel<0><<<dim3(DD / 64, NN / 64), 256, GEMM_SMEM>>>(p_h1, W2, bf2, p_f2, NN, DD, 2 * DD);

    ln_kernel<<<NN, 256>>>(p_x2, p_f2, g2, beta2, out);

    cudaEventDestroy(eFork);
    cudaEventDestroy(eJoin);
    cudaStreamDestroy(s2);
}

// round 15
// speedup vs baseline: 1.0390x; 1.0390x over previous
#include <cuda_runtime.h>
#include <cuda_bf16.h>
#include <math.h>
#include <stdint.h>

#define NN 4096
#define DD 256
#define HH 4
#define HD 64
#define D3 768
#define BUCKET 96

#define CVT_BF16X2_F32(result, a, b) \
    asm("cvt.rn.satfinite.bf16x2.f32 %0, %1, %2;" : "=r"(result) : "f"(b), "f"(a))

__device__ __forceinline__ float fexp2(float x) {
    float y;
    asm("ex2.approx.ftz.f32 %0, %1;" : "=f"(y) : "f"(x));
    return y;
}
__device__ __forceinline__ uint32_t smem_u32(const void* p) {
    uint32_t a;
    asm("{ .reg .u64 t; cvta.to.shared.u64 t, %1; cvt.u32.u64 %0, t; }" : "=r"(a) : "l"(p));
    return a;
}
#define CP_ASYNC16(dst, src) \
    asm volatile("cp.async.cg.shared.global [%0], [%1], 16;" :: "r"(dst), "l"(src))
#define CP_COMMIT() asm volatile("cp.async.commit_group;" ::: "memory")
#define CP_WAIT(n)  asm volatile("cp.async.wait_group %0;" :: "n"(n) : "memory")

__device__ __forceinline__ void mma16816(float c[4],
                                         uint32_t a0, uint32_t a1, uint32_t a2, uint32_t a3,
                                         uint32_t b0, uint32_t b1) {
    asm volatile("mma.sync.aligned.m16n8k16.row.col.f32.bf16.bf16.f32 "
                 "{%0,%1,%2,%3}, {%4,%5,%6,%7}, {%8,%9}, {%0,%1,%2,%3};"
                 : "+f"(c[0]), "+f"(c[1]), "+f"(c[2]), "+f"(c[3])
                 : "r"(a0), "r"(a1), "r"(a2), "r"(a3), "r"(b0), "r"(b1));
}
__device__ __forceinline__ void mma1688t(float c[4],
                                         uint32_t a0, uint32_t a1, uint32_t a2, uint32_t a3,
                                         uint32_t b0, uint32_t b1) {
    asm volatile("mma.sync.aligned.m16n8k8.row.col.f32.tf32.tf32.f32 "
                 "{%0,%1,%2,%3}, {%4,%5,%6,%7}, {%8,%9}, {%0,%1,%2,%3};"
                 : "+f"(c[0]), "+f"(c[1]), "+f"(c[2]), "+f"(c[3])
                 : "r"(a0), "r"(a1), "r"(a2), "r"(a3), "r"(b0), "r"(b1));
}

// ======================= scratch (device globals; BSS-zeroed at load) =======
__device__ float g_h   [NN * DD];
__device__ float g_x1  [NN * DD];
__device__ float g_attn[NN * DD];
__device__ float g_ao  [NN * DD];
__device__ float g_x2  [NN * DD];
__device__ float g_h1  [NN * 2 * DD];
__device__ float g_f2  [NN * DD];
__device__ float g_dinv[NN];
__device__ int   g_deg [NN];
__device__ int   g_degc[NN];
__device__ int   g_ebuf[NN * BUCKET];
__device__ __align__(16) __nv_bfloat16 g_qb [HH * NN * HD];
__device__ __align__(16) __nv_bfloat16 g_kb [HH * NN * HD];
__device__ __align__(16) __nv_bfloat16 g_vtb[HH * HD * NN];

#define QSCALE (0.125f * 1.4426950408889634f)

// ======================= bucketed CSR (one atomic pass) =====================
__global__ void count_fill_kernel(const int* __restrict__ src, const int* __restrict__ dst,
                                  int* __restrict__ deg, int* __restrict__ ebuf, int E) {
    int e = blockIdx.x * blockDim.x + threadIdx.x;
    if (e < E) {
        int d = dst[e];
        int pos = atomicAdd(&deg[d], 1);
        ebuf[d * BUCKET + pos] = src[e];
    }
}
__global__ void dinv_kernel(int* __restrict__ deg, int* __restrict__ degc,
                            float* __restrict__ dinv) {
    int i = blockIdx.x * blockDim.x + threadIdx.x;
    if (i < NN) {
        int d = deg[i];
        dinv[i] = rsqrtf((float)d + 1.0f);
        degc[i] = d;
        deg[i] = 0;
    }
}

// ======================= fused GCN gather + self-loop + LN1 =================
// 64 threads x float4.
__global__ __launch_bounds__(64)
void gcn_ln_kernel(const float* __restrict__ x, const float* __restrict__ h,
                   const float* __restrict__ dinv,
                   const int* __restrict__ degc, const int* __restrict__ ebuf,
                   const float* __restrict__ b_gcn,
                   const float* __restrict__ gln, const float* __restrict__ beta,
                   float* __restrict__ x1) {
    const int i = blockIdx.x;
    const int tid = threadIdx.x;

    __shared__ __align__(8) float2 s_ec[BUCKET];
    __shared__ float ws1[2], ws2[2], bc[2];
    __shared__ int   s_dg;
    __shared__ float s_di;

    if (tid == 0) { s_dg = degc[i]; s_di = dinv[i]; }
    __syncthreads();
    const int dg = s_dg;
    const float di = s_di;

    for (int j = tid; j < dg; j += 64) {
        int s = ebuf[i * BUCKET + j];
        float2 ec;
        ec.x = __int_as_float(s);
        ec.y = dinv[s] * di;
        s_ec[j] = ec;
    }
    __syncthreads();

    const char* hb = (const char*)(h + 4 * tid);
    float4 acc = make_float4(0.f, 0.f, 0.f, 0.f);
    int j = 0;
    for (; j + 3 < dg; j += 4) {
        float2 e0 = s_ec[j],     e1 = s_ec[j + 1];
        float2 e2 = s_ec[j + 2], e3 = s_ec[j + 3];
        float4 v0 = *(const float4*)(hb + ((uint32_t)__float_as_int(e0.x) << 10));
        float4 v1 = *(const float4*)(hb + ((uint32_t)__float_as_int(e1.x) << 10));
        float4 v2 = *(const float4*)(hb + ((uint32_t)__float_as_int(e2.x) << 10));
        float4 v3 = *(const float4*)(hb + ((uint32_t)__float_as_int(e3.x) << 10));
        acc.x += v0.x * e0.y + v1.x * e1.y + v2.x * e2.y + v3.x * e3.y;
        acc.y += v0.y * e0.y + v1.y * e1.y + v2.y * e2.y + v3.y * e3.y;
        acc.z += v0.z * e0.y + v1.z * e1.y + v2.z * e2.y + v3.z * e3.y;
        acc.w += v0.w * e0.y + v1.w * e1.y + v2.w * e2.y + v3.w * e3.y;
    }
    for (; j < dg; j++) {
        float2 e = s_ec[j];
        float4 v = *(const float4*)(hb + ((uint32_t)__float_as_int(e.x) << 10));
        acc.x += v.x * e.y; acc.y += v.y * e.y;
        acc.z += v.z * e.y; acc.w += v.w * e.y;
    }

    const float dii = di * di;
    float4 xv = *(const float4*)&x[(size_t)i * DD + 4 * tid];
    float4 hv = *(const float4*)&h[(size_t)i * DD + 4 * tid];
    float4 bg = *(const float4*)&b_gcn[4 * tid];
    float4 v;
    v.x = xv.x + acc.x + hv.x * dii + bg.x;
    v.y = xv.y + acc.y + hv.y * dii + bg.y;
    v.z = xv.z + acc.z + hv.z * dii + bg.z;
    v.w = xv.w + acc.w + hv.w * dii + bg.w;

    float s1v = v.x + v.y + v.z + v.w;
    float s2v = v.x * v.x + v.y * v.y + v.z * v.z + v.w * v.w;
    #pragma unroll
    for (int off = 16; off > 0; off >>= 1) {
        s1v += __shfl_xor_sync(0xffffffffu, s1v, off);
        s2v += __shfl_xor_sync(0xffffffffu, s2v, off);
    }
    int w = tid >> 5;
    if ((tid & 31) == 0) { ws1[w] = s1v; ws2[w] = s2v; }
    __syncthreads();
    if (tid == 0) {
        float t1 = ws1[0] + ws1[1];
        float t2 = ws2[0] + ws2[1];
        float mean = t1 * (1.0f / DD);
        float var  = t2 * (1.0f / DD) - mean * mean;
        bc[0] = mean; bc[1] = rsqrtf(var + 1e-5f);
    }
    __syncthreads();
    float4 gv = *(const float4*)&gln[4 * tid];
    float4 bv = *(const float4*)&beta[4 * tid];
    float4 o;
    o.x = (v.x - bc[0]) * bc[1] * gv.x + bv.x;
    o.y = (v.y - bc[0]) * bc[1] * gv.y + bv.y;
    o.z = (v.z - bc[0]) * bc[1] * gv.z + bv.z;
    o.w = (v.w - bc[0]) * bc[1] * gv.w + bv.w;
    *(float4*)&x1[(size_t)i * DD + 4 * tid] = o;
}

// ======================= layernorm (residual), 64 thr x float4 ==============
__global__ __launch_bounds__(64)
void ln_kernel(const float* __restrict__ a, const float* __restrict__ b,
               const float* __restrict__ g, const float* __restrict__ beta,
               float* __restrict__ out) {
    const int r = blockIdx.x, tid = threadIdx.x;
    __shared__ float ws1[2], ws2[2], bc[2];

    float4 av = *(const float4*)&a[(size_t)r * DD + 4 * tid];
    float4 bv = *(const float4*)&b[(size_t)r * DD + 4 * tid];
    float4 v;
    v.x = av.x + bv.x; v.y = av.y + bv.y;
    v.z = av.z + bv.z; v.w = av.w + bv.w;

    float s1 = v.x + v.y + v.z + v.w;
    float s2 = v.x * v.x + v.y * v.y + v.z * v.z + v.w * v.w;
    #pragma unroll
    for (int off = 16; off > 0; off >>= 1) {
        s1 += __shfl_xor_sync(0xffffffffu, s1, off);
        s2 += __shfl_xor_sync(0xffffffffu, s2, off);
    }
    int w = tid >> 5;
    if ((tid & 31) == 0) { ws1[w] = s1; ws2[w] = s2; }
    __syncthreads();
    if (tid == 0) {
        float t1 = ws1[0] + ws1[1];
        float t2 = ws2[0] + ws2[1];
        float mean = t1 * (1.0f / DD);
        float var  = t2 * (1.0f / DD) - mean * mean;
        bc[0] = mean; bc[1] = rsqrtf(var + 1e-5f);
    }
    __syncthreads();
    float4 gv = *(const float4*)&g[4 * tid];
    float4 be = *(const float4*)&beta[4 * tid];
    float4 o;
    o.x = (v.x - bc[0]) * bc[1] * gv.x + be.x;
    o.y = (v.y - bc[0]) * bc[1] * gv.y + be.y;
    o.z = (v.z - bc[0]) * bc[1] * gv.z + be.z;
    o.w = (v.w - bc[0]) * bc[1] * gv.w + be.w;
    *(float4*)&out[(size_t)r * DD + 4 * tid] = o;
}

// ======================= tf32 HMMA GEMM, 3-stage cp.async ===================
#define ALD 36
#define BLD 72
#define ASZ (64 * ALD)
#define BSZ (32 * BLD)
#define GSTAGES 3
#define GEMM_SMEM ((GSTAGES * (ASZ + BSZ)) * 4)
template <int MODE>
__global__ __launch_bounds__(256)
void tgemm_kernel(const float* __restrict__ A, const float* __restrict__ B,
                  const float* __restrict__ bias, float* __restrict__ C,
                  int M, int N, int K) {
    extern __shared__ float dsm[];
    float* As = dsm;
    float* Bs = dsm + GSTAGES * ASZ;
    const int tid = threadIdx.x;
    const int lane = tid & 31;
    const int g = lane >> 2, t = lane & 3;
    const int wid = tid >> 5;
    const int wm = (wid >> 2) * 32;
    const int wn = (wid & 3) * 16;
    const int bm = blockIdx.y * 64, bn = blockIdx.x * 64;

    const uint32_t sA = smem_u32(As);
    const uint32_t sB = smem_u32(Bs);
    const int nk = K / 32;

    auto load_stage = [&](int k0, int s) {
        #pragma unroll
        for (int i = 0; i < 2; i++) {
            int p = tid + 256 * i;
            int row = p >> 3, c = p & 7;
            uint32_t dst = sA + (uint32_t)(s * ASZ + row * ALD + c * 4) * 4u;
            CP_ASYNC16(dst, &A[(size_t)(bm + row) * K + k0 + c * 4]);
        }
        #pragma unroll
        for (int i = 0; i < 2; i++) {
            int p = tid + 256 * i;
            int row = p >> 4, c = p & 15;
            uint32_t dst = sB + (uint32_t)(s * BSZ + row * BLD + c * 4) * 4u;
            CP_ASYNC16(dst, &B[(size_t)(k0 + row) * N + bn + c * 4]);
        }
        CP_COMMIT();
    };

    float acc[2][2][4] = {};

    load_stage(0, 0);
    if (nk > 1) load_stage(32, 1); else CP_COMMIT();
    for (int it = 0; it < nk; it++) {
        if (it + 2 < nk) load_stage((it + 2) * 32, (it + 2) % GSTAGES);
        else             CP_COMMIT();
        CP_WAIT(2);
        __syncthreads();

        const float* a_ = As + (it % GSTAGES) * ASZ;
        const float* b_ = Bs + (it % GSTAGES) * BSZ;
        #pragma unroll
        for (int kk = 0; kk < 4; kk++) {
            const int kb = kk * 8;
            uint32_t a[2][4];
            #pragma unroll
            for (int mi = 0; mi < 2; mi++) {
                int r = wm + mi * 16 + g;
                a[mi][0] = __float_as_uint(a_[r * ALD + kb + t]);
                a[mi][1] = __float_as_uint(a_[(r + 8) * ALD + kb + t]);
                a[mi][2] = __float_as_uint(a_[r * ALD + kb + t + 4]);
                a[mi][3] = __float_as_uint(a_[(r + 8) * ALD + kb + t + 4]);
            }
            #pragma unroll
            for (int nj = 0; nj < 2; nj++) {
                int cn = wn + nj * 8 + g;
                uint32_t b0 = __float_as_uint(b_[(kb + t) * BLD + cn]);
                uint32_t b1 = __float_as_uint(b_[(kb + t + 4) * BLD + cn]);
                mma1688t(acc[0][nj], a[0][0], a[0][1], a[0][2], a[0][3], b0, b1);
                mma1688t(acc[1][nj], a[1][0], a[1][1], a[1][2], a[1][3], b0, b1);
            }
        }
        __syncthreads();
    }

    #pragma unroll
    for (int nj = 0; nj < 2; nj++) {
        int col = bn + wn + nj * 8 + 2 * t;
        float2 bb = make_float2(0.f, 0.f);
        if (bias) bb = *(const float2*)&bias[col];
        #pragma unroll
        for (int mi = 0; mi < 2; mi++) {
            int row = bm + wm + mi * 16 + g;
            float2 v0 = make_float2(acc[mi][nj][0] + bb.x, acc[mi][nj][1] + bb.y);
            float2 v1 = make_float2(acc[mi][nj][2] + bb.x, acc[mi][nj][3] + bb.y);
            if (MODE == 1) {
                v0.x = fmaxf(v0.x, 0.f); v0.y = fmaxf(v0.y, 0.f);
                v1.x = fmaxf(v1.x, 0.f); v1.y = fmaxf(v1.y, 0.f);
            }
            if (MODE == 2) {
                if (col < 256) {            // Q, scaled
                    int hh = col >> 6, d = col & 63;
                    uint32_t p0, p1;
                    CVT_BF16X2_F32(p0, v0.x * QSCALE, v0.y * QSCALE);
                    CVT_BF16X2_F32(p1, v1.x * QSCALE, v1.y * QSCALE);
                    *(uint32_t*)&g_qb[(size_t)(hh * NN + row) * HD + d] = p0;
                    *(uint32_t*)&g_qb[(size_t)(hh * NN + row + 8) * HD + d] = p1;
                } else if (col < 512) {     // K
                    int c = col - 256;
                    int hh = c >> 6, d = c & 63;
                    uint32_t p0, p1;
                    CVT_BF16X2_F32(p0, v0.x, v0.y);
                    CVT_BF16X2_F32(p1, v1.x, v1.y);
                    *(uint32_t*)&g_kb[(size_t)(hh * NN + row) * HD + d] = p0;
                    *(uint32_t*)&g_kb[(size_t)(hh * NN + row + 8) * HD + d] = p1;
                } else {                    // V, transposed
                    int c = col - 512;
                    int hh = c >> 6, d = c & 63;
                    __nv_bfloat16* v_d0 = g_vtb + (size_t)(hh * HD + d) * NN;
                    __nv_bfloat16* v_d1 = g_vtb + (size_t)(hh * HD + d + 1) * NN;
                    v_d0[row]     = __float2bfloat16(v0.x);
                    v_d1[row]     = __float2bfloat16(v0.y);
                    v_d0[row + 8] = __float2bfloat16(v1.x);
                    v_d1[row + 8] = __float2bfloat16(v1.y);
                }
            } else {
                *(float2*)&C[(size_t)row * N + col] = v0;
                *(float2*)&C[(size_t)(row + 8) * N + col] = v1;
            }
        }
    }
}

// ======================= HMMA flash attention ================================
#define QROWB 144
#define QS_BYTES (64 * QROWB)
#define KV_BYTES (64 * QROWB)
#define ATT_SMEM (QS_BYTES + 4 * KV_BYTES)
__global__ __launch_bounds__(128)
void attn_mma_kernel(float* __restrict__ attn_out) {
    extern __shared__ __align__(16) uint8_t asmem[];
    uint8_t* Qs = asmem;
    uint8_t* Ks = asmem + QS_BYTES;
    uint8_t* Vs = asmem + QS_BYTES + 2 * KV_BYTES;

    const int tid = threadIdx.x;
    const int wid = tid >> 5;
    const int lane = tid & 31;
    const int g = lane >> 2;
    const int t = lane & 3;
    const int hh = blockIdx.y;
    const int qt = blockIdx.x;

    const uint32_t sK = smem_u32(Ks);
    const uint32_t sV = smem_u32(Vs);

    auto load_kv = [&](int kt, int s) {
        const char* kbase = (const char*)(g_kb + (size_t)(hh * NN + kt * 64) * HD);
        #pragma unroll
        for (int i = 0; i < 4; i++) {
            int p = tid + 128 * i;
            int row = p >> 3, c = p & 7;
            CP_ASYNC16(sK + (uint32_t)(s * KV_BYTES + row * QROWB + c * 16),
                       kbase + row * 128 + c * 16);
            const char* vbase = (const char*)(g_vtb + (size_t)(hh * HD + row) * NN + kt * 64);
            CP_ASYNC16(sV + (uint32_t)(s * KV_BYTES + row * QROWB + c * 16),
                       vbase + c * 16);
        }
        CP_COMMIT();
    };

    {
        const uint4* src = (const uint4*)(g_qb + (size_t)(hh * NN + qt * 64) * HD);
        #pragma unroll
        for (int i = 0; i < 4; i++) {
            int p = tid + 128 * i;
            int row = p >> 3, c = p & 7;
            *(uint4*)&Qs[row * QROWB + c * 16] = src[p];
        }
    }
    load_kv(0, 0);
    __syncthreads();

    uint32_t qf[4][4];
    {
        int r0 = wid * 16 + g;
        #pragma unroll
        for (int kc = 0; kc < 4; kc++) {
            int cb = (kc * 16 + 2 * t) * 2;
            qf[kc][0] = *(const uint32_t*)&Qs[r0 * QROWB + cb];
            qf[kc][1] = *(const uint32_t*)&Qs[(r0 + 8) * QROWB + cb];
            qf[kc][2] = *(const uint32_t*)&Qs[r0 * QROWB + cb + 16];
            qf[kc][3] = *(const uint32_t*)&Qs[(r0 + 8) * QROWB + cb + 16];
        }
    }

    float O[8][4];
    #pragma unroll
    for (int n = 0; n < 8; n++)
        #pragma unroll
        for (int i = 0; i < 4; i++) O[n][i] = 0.f;
    float l0 = 0.f, l1 = 0.f;

    for (int kt = 0; kt < NN / 64; kt++) {
        if (kt + 1 < NN / 64) load_kv(kt + 1, (kt + 1) & 1);
        else                  CP_COMMIT();
        CP_WAIT(1);
        __syncthreads();

        const uint8_t* kb = Ks + (kt & 1) * KV_BYTES;
        const uint8_t* vb = Vs + (kt & 1) * KV_BYTES;

        float S[8][4];
        #pragma unroll
        for (int n = 0; n < 8; n++)
            #pragma unroll
            for (int i = 0; i < 4; i++) S[n][i] = 0.f;
        #pragma unroll
        for (int kc = 0; kc < 4; kc++) {
            int cb = (kc * 16 + 2 * t) * 2;
            #pragma unroll
            for (int n = 0; n < 8; n++) {
                uint32_t b0 = *(const uint32_t*)&kb[(n * 8 + g) * QROWB + cb];
                uint32_t b1 = *(const uint32_t*)&kb[(n * 8 + g) * QROWB + cb + 16];
                mma16816(S[n], qf[kc][0], qf[kc][1], qf[kc][2], qf[kc][3], b0, b1);
            }
        }

        uint32_t pb[8][2];
        #pragma unroll
        for (int n = 0; n < 8; n++) {
            float p0 = fexp2(S[n][0]);
            float p1 = fexp2(S[n][1]);
            float p2 = fexp2(S[n][2]);
            float p3 = fexp2(S[n][3]);
            l0 += p0 + p1; l1 += p2 + p3;
            CVT_BF16X2_F32(pb[n][0], p0, p1);
            CVT_BF16X2_F32(pb[n][1], p2, p3);
        }

        #pragma unroll
        for (int kc = 0; kc < 4; kc++) {
            uint32_t a0 = pb[2 * kc][0], a1 = pb[2 * kc][1];
            uint32_t a2 = pb[2 * kc + 1][0], a3 = pb[2 * kc + 1][1];
            int cb = (kc * 16 + 2 * t) * 2;
            #pragma unroll
            for (int n = 0; n < 8; n++) {
                uint32_t b0 = *(const uint32_t*)&vb[(n * 8 + g) * QROWB + cb];
                uint32_t b1 = *(const uint32_t*)&vb[(n * 8 + g) * QROWB + cb + 16];
                mma16816(O[n], a0, a1, a2, a3, b0, b1);
            }
        }
        __syncthreads();
    }

    l0 += __shfl_xor_sync(0xffffffffu, l0, 1);
    l0 += __shfl_xor_sync(0xffffffffu, l0, 2);
    l1 += __shfl_xor_sync(0xffffffffu, l1, 1);
    l1 += __shfl_xor_sync(0xffffffffu, l1, 2);

    float inv0 = 1.0f / l0, inv1 = 1.0f / l1;
    int r0 = qt * 64 + wid * 16 + g;
    #pragma unroll
    for (int n = 0; n < 8; n++) {
        int dcol = hh * HD + n * 8 + 2 * t;
        float2 v0 = make_float2(O[n][0] * inv0, O[n][1] * inv0);
        float2 v1 = make_float2(O[n][2] * inv1, O[n][3] * inv1);
        *(float2*)&attn_out[(size_t)r0 * DD + dcol] = v0;
        *(float2*)&attn_out[(size_t)(r0 + 8) * DD + dcol] = v1;
    }
}

// ======================= launch =============================================
static float* sym_f(const void* sym) {
    void* p = nullptr;
    cudaGetSymbolAddress(&p, sym);
    return (float*)p;
}

extern "C" void kernel_launch(void* const* d_in, const int* in_sizes, int n_in,
                              void* d_out, int out_size) {
    const float* x      = (const float*)d_in[0];
    const int*   edges  = (const int*)  d_in[1];
    const float* W_gcn  = (const float*)d_in[2];
    const float* b_gcn  = (const float*)d_in[3];
    const float* w_qkv  = (const float*)d_in[4];
    const float* b_qkv  = (const float*)d_in[5];
    const float* w_out  = (const float*)d_in[6];
    const float* b_out  = (const float*)d_in[7];
    const float* g1l    = (const float*)d_in[8];
    const float* beta1l = (const float*)d_in[9];
    const float* g1a    = (const float*)d_in[10];
    const float* beta1a = (const float*)d_in[11];
    const float* W1     = (const float*)d_in[12];
    const float* bf1    = (const float*)d_in[13];
    const float* W2     = (const float*)d_in[14];
    const float* bf2    = (const float*)d_in[15];
    const float* g2     = (const float*)d_in[16];
    const float* beta2  = (const float*)d_in[17];
    float* out = (float*)d_out;

    float* p_h    = sym_f(g_h);
    float* p_x1   = sym_f(g_x1);
    float* p_attn = sym_f(g_attn);
    float* p_ao   = sym_f(g_ao);
    float* p_x2   = sym_f(g_x2);
    float* p_h1   = sym_f(g_h1);
    float* p_f2   = sym_f(g_f2);
    float* p_dinv = sym_f(g_dinv);
    int*   p_deg  = (int*)sym_f(g_deg);
    int*   p_degc = (int*)sym_f(g_degc);
    int*   p_ebuf = (int*)sym_f(g_ebuf);

    const int E = in_sizes[1] / 2;
    const int* e_src = edges;
    const int* e_dst = edges + E;

    cudaFuncSetAttribute(tgemm_kernel<0>, cudaFuncAttributeMaxDynamicSharedMemorySize, GEMM_SMEM);
    cudaFuncSetAttribute(tgemm_kernel<1>, cudaFuncAttributeMaxDynamicSharedMemorySize, GEMM_SMEM);
    cudaFuncSetAttribute(tgemm_kernel<2>, cudaFuncAttributeMaxDynamicSharedMemorySize, GEMM_SMEM);
    cudaFuncSetAttribute(attn_mma_kernel, cudaFuncAttributeMaxDynamicSharedMemorySize, ATT_SMEM);

    count_fill_kernel<<<(E + 255) / 256, 256>>>(e_src, e_dst, p_deg, p_ebuf, E);
    dinv_kernel<<<NN / 256, 256>>>(p_deg, p_degc, p_dinv);

    tgemm_kernel<0><<<dim3(DD / 64, NN / 64), 256, GEMM_SMEM>>>(x, W_gcn, nullptr, p_h, NN, DD, DD);

    gcn_ln_kernel<<<NN, 64>>>(x, p_h, p_dinv, p_degc, p_ebuf, b_gcn, g1l, beta1l, p_x1);

    tgemm_kernel<2><<<dim3(D3 / 64, NN / 64), 256, GEMM_SMEM>>>(p_x1, w_qkv, b_qkv, nullptr, NN, D3, DD);

    attn_mma_kernel<<<dim3(NN / 64, HH), 128, ATT_SMEM>>>(p_attn);

    tgemm_kernel<0><<<dim3(DD / 64, NN / 64), 256, GEMM_SMEM>>>(p_attn, w_out, b_out, p_ao, NN, DD, DD);

    ln_kernel<<<NN, 64>>>(p_x1, p_ao, g1a, beta1a, p_x2);

    tgemm_kernel<1><<<dim3(2 * DD / 64, NN / 64), 256, GEMM_SMEM>>>(p_x2, W1, bf1, p_h1, NN, 2 * DD, DD);
    tgemm_kernel<0><<<dim3(DD / 64, NN / 64), 256, GEMM_SMEM>>>(p_h1, W2, bf2, p_f2, NN, DD, 2 * DD);

    ln_kernel<<<NN, 64>>>(p_x2, p_f2, g2, beta2, out);
}